// round 17
// baseline (speedup 1.0000x reference)
#include <cuda_runtime.h>
#include <cuda_fp16.h>
#include <math.h>
#include <stdint.h>

// ---------------- problem constants ----------------
#define CDIM    384
#define NHEAD   12
#define TOK     100352        // 32*3136
#define EPS     1e-5f
#define SCALE   0.17677669529663687f  // 1/sqrt(32)

// ---------------- scratch (device globals; no allocations) ----------------
__device__ __half g_h  [(size_t)TOK * 384];
__device__ __half g_qkv[(size_t)TOK * 1152];
__device__ __half g_o  [(size_t)TOK * 384];
__device__ float  g_xa [(size_t)TOK * 384];   // residual stream stays fp32
__device__ __half g_y  [(size_t)TOK * 384];
__device__ __half g_u  [(size_t)TOK * 1536];
__device__ __half g_wt [1769472];             // transposed fp16 weights
__device__ float  g_bias[4 * NHEAD * 2401];   // fused rpb+mask per (type, head)

#define WT_QKV 0
#define WT_PROJ 442368
#define WT_FC1 589824
#define WT_FC2 1179648

// ---------------- small PTX helpers ----------------
__device__ __forceinline__ uint32_t smem_u32(const void* p){
    uint32_t a;
    asm("{ .reg .u64 t; cvta.to.shared.u64 t, %1; cvt.u32.u64 %0, t; }" : "=r"(a) : "l"(p));
    return a;
}
__device__ __forceinline__ void cp16(uint32_t d, const void* s){
    asm volatile("cp.async.cg.shared.global [%0], [%1], 16;" :: "r"(d), "l"(s));
}
__device__ __forceinline__ void cp_commit(){ asm volatile("cp.async.commit_group;"); }
__device__ __forceinline__ void cp_wait1(){ asm volatile("cp.async.wait_group 1;" ::: "memory"); }
__device__ __forceinline__ void cp_wait0(){ asm volatile("cp.async.wait_group 0;" ::: "memory"); }

// fp16 m16n8k16 mma, fp32 accumulate
__device__ __forceinline__ void mma16(float* d, uint32_t a0, uint32_t a1,
                                      uint32_t a2, uint32_t a3,
                                      uint32_t b0, uint32_t b1){
    asm volatile("mma.sync.aligned.m16n8k16.row.col.f32.f16.f16.f32 "
        "{%0,%1,%2,%3}, {%4,%5,%6,%7}, {%8,%9}, {%0,%1,%2,%3};"
        : "+f"(d[0]), "+f"(d[1]), "+f"(d[2]), "+f"(d[3])
        : "r"(a0), "r"(a1), "r"(a2), "r"(a3), "r"(b0), "r"(b1));
}

__device__ __forceinline__ void ldsm4(uint32_t& r0, uint32_t& r1,
                                      uint32_t& r2, uint32_t& r3, uint32_t addr){
    asm volatile("ldmatrix.sync.aligned.m8n8.x4.shared.b16 {%0,%1,%2,%3}, [%4];"
        : "=r"(r0), "=r"(r1), "=r"(r2), "=r"(r3) : "r"(addr));
}

// window-order row t <-> original-order row (self-inverse map)
__device__ __forceinline__ int winrow_to_orig(int t) {
    int b   = t / 3136;
    int rem = t - b * 3136;
    int w   = rem / 49;
    int n   = rem - w * 49;
    int wr = w >> 3, wc = w & 7;
    int r  = n / 7,  c  = n - r * 7;
    int gh = wr * 7 + r + 3; if (gh >= 56) gh -= 56;
    int gw = wc * 7 + c + 3; if (gw >= 56) gw -= 56;
    return b * 3136 + gh * 56 + gw;
}

// ---------------- LayerNorm -> fp16, warp-per-token, no smem/syncs ---------
template<int GATHER>
__global__ void __launch_bounds__(128) ln_kernel(
    const float* __restrict__ x, const float* __restrict__ g,
    const float* __restrict__ b, __half* __restrict__ out)
{
    int warp = threadIdx.x >> 5, lane = threadIdx.x & 31;
    int t    = (blockIdx.x << 2) + warp;
    int src  = GATHER ? winrow_to_orig(t) : t;

    const float4* xr = (const float4*)(x + (size_t)src * CDIM) + lane * 3;
    float4 v0 = xr[0], v1 = xr[1], v2 = xr[2];

    float s  = v0.x + v0.y + v0.z + v0.w + v1.x + v1.y + v1.z + v1.w
             + v2.x + v2.y + v2.z + v2.w;
    float sq = v0.x*v0.x + v0.y*v0.y + v0.z*v0.z + v0.w*v0.w
             + v1.x*v1.x + v1.y*v1.y + v1.z*v1.z + v1.w*v1.w
             + v2.x*v2.x + v2.y*v2.y + v2.z*v2.z + v2.w*v2.w;
    #pragma unroll
    for (int off = 16; off; off >>= 1) {
        s  += __shfl_xor_sync(~0u, s,  off);
        sq += __shfl_xor_sync(~0u, sq, off);
    }
    float mean = s * (1.0f / CDIM);
    float var  = sq * (1.0f / CDIM) - mean * mean;
    float inv  = rsqrtf(var + EPS);

    const float4* gp = (const float4*)g + lane * 3;
    const float4* bp = (const float4*)b + lane * 3;
    float4 g0 = gp[0], g1 = gp[1], g2 = gp[2];
    float4 b0 = bp[0], b1 = bp[1], b2 = bp[2];

    __half2* op = (__half2*)(out + (size_t)t * CDIM + lane * 12);
    op[0] = __floats2half2_rn((v0.x - mean) * inv * g0.x + b0.x, (v0.y - mean) * inv * g0.y + b0.y);
    op[1] = __floats2half2_rn((v0.z - mean) * inv * g0.z + b0.z, (v0.w - mean) * inv * g0.w + b0.w);
    op[2] = __floats2half2_rn((v1.x - mean) * inv * g1.x + b1.x, (v1.y - mean) * inv * g1.y + b1.y);
    op[3] = __floats2half2_rn((v1.z - mean) * inv * g1.z + b1.z, (v1.w - mean) * inv * g1.w + b1.w);
    op[4] = __floats2half2_rn((v2.x - mean) * inv * g2.x + b2.x, (v2.y - mean) * inv * g2.y + b2.y);
    op[5] = __floats2half2_rn((v2.z - mean) * inv * g2.z + b2.z, (v2.w - mean) * inv * g2.w + b2.w);
}

// ---------------- all 4 weight transposes in ONE launch ---------------------
__global__ void __launch_bounds__(256) transpose_all(
    const float* __restrict__ qkv_w, const float* __restrict__ proj_w,
    const float* __restrict__ fc1_w, const float* __restrict__ fc2_w,
    __half* __restrict__ wt)
{
    __shared__ float tile[32][33];
    int bid = blockIdx.x;
    const float* in; __half* out; int K, N, tIdx;
    if (bid < 432)       { in = qkv_w;  out = wt + WT_QKV;  K = 384;  N = 1152; tIdx = bid; }
    else if (bid < 576)  { in = proj_w; out = wt + WT_PROJ; K = 384;  N = 384;  tIdx = bid - 432; }
    else if (bid < 1152) { in = fc1_w;  out = wt + WT_FC1;  K = 384;  N = 1536; tIdx = bid - 576; }
    else                 { in = fc2_w;  out = wt + WT_FC2;  K = 1536; N = 384;  tIdx = bid - 1152; }
    int ntx = N >> 5;
    int by = tIdx / ntx, bx = tIdx - by * ntx;
    int k0 = by * 32, n0 = bx * 32;
    int tx = threadIdx.x & 31, ty = threadIdx.x >> 5;
    #pragma unroll
    for (int i = ty; i < 32; i += 8)
        tile[i][tx] = in[(size_t)(k0 + i) * N + n0 + tx];
    __syncthreads();
    #pragma unroll
    for (int i = ty; i < 32; i += 8)
        out[(size_t)(n0 + i) * K + k0 + tx] = __float2half(tile[tx][i]);
}

// ---------------- fused rel-pos bias + shifted-window mask -----------------
__global__ void __launch_bounds__(256) prep_bias(
    const float* __restrict__ bias_table, float* __restrict__ gb)
{
    int type = blockIdx.x / NHEAD, head = blockIdx.x - type * NHEAD;
    int rowB = type >> 1, colB = type & 1;
    for (int e = threadIdx.x; e < 2401; e += 256) {
        int i = e / 49, j = e - i * 49;
        int ih = i / 7, iw = i - ih * 7;
        int jh = j / 7, jw = j - jh * 7;
        float v = bias_table[((ih - jh + 6) * 13 + (iw - jw + 6)) * NHEAD + head];
        int li = (rowB ? (ih < 4 ? 1 : 2) : 0) * 3 + (colB ? (iw < 4 ? 1 : 2) : 0);
        int lj = (rowB ? (jh < 4 ? 1 : 2) : 0) * 3 + (colB ? (jw < 4 ? 1 : 2) : 0);
        if (li != lj) v -= 100.0f;
        gb[blockIdx.x * 2401 + e] = v;
    }
}

// ---------------- FP16 mma.sync GEMM (at the mma.sync f32-acc roofline) -----
#define PITCH_B 144      // bytes per row (72 halves)
#define STG_B   36864    // bytes per stage
#define SMEM_SZ 110592   // 3 stages

template<int MODE>
__global__ void __launch_bounds__(128, 2) tc_gemm(
    const __half* __restrict__ A, const __half* __restrict__ Bt,
    const float* __restrict__ bias, const float* __restrict__ res,
    void* __restrict__ Cv, int N, int K)
{
    extern __shared__ __align__(16) char smem[];
    int tid  = threadIdx.x;
    int lane = tid & 31;
    int wid  = tid >> 5;           // 0..3
    int warp_m = wid >> 1;         // 2 x 64 rows
    int warp_n = wid & 1;          // 2 x 64 cols
    int m0 = blockIdx.y << 7, n0 = blockIdx.x << 7;

    const __half* Arow = A  + (size_t)m0 * K;
    const __half* Brow = Bt + (size_t)n0 * K;
    const int nst = K >> 6;

    uint32_t sbase = smem_u32(smem);

    int ldrow = tid >> 3;
    int ldc   = tid & 7;

    auto issue_stage = [&](int s, int buf) {
        int kt = s << 6;
        uint32_t bA = sbase + (uint32_t)buf * STG_B;
        uint32_t bB = bA + 18432;
        #pragma unroll
        for (int p = 0; p < 8; ++p) {
            int row = ldrow + (p << 4);
            uint32_t doff = (uint32_t)row * PITCH_B + (uint32_t)(ldc << 4);
            cp16(bA + doff, Arow + (size_t)row * K + kt + (ldc << 3));
            cp16(bB + doff, Brow + (size_t)row * K + kt + (ldc << 3));
        }
        cp_commit();
    };

    float acc[4][8][4];
    #pragma unroll
    for (int i = 0; i < 4; i++)
        #pragma unroll
        for (int j = 0; j < 8; j++)
            #pragma unroll
            for (int r = 0; r < 4; r++) acc[i][j][r] = 0.0f;

    issue_stage(0, 0);
    issue_stage(1, 1);

    int lr = lane >> 2;
    int lc = lane & 3;

    uint32_t a_row = (uint32_t)((warp_m << 6) + (lane & 15));
    uint32_t a_off = a_row * PITCH_B + ((uint32_t)(lane >> 4) << 4);
    uint32_t b_row = (uint32_t)((warp_n << 6) + (lane & 7) + (((lane >> 4) & 1) << 3));
    uint32_t b_off = b_row * PITCH_B + (((uint32_t)(lane >> 3) & 1) << 4);

    for (int s = 0; s < nst; ++s) {
        int buf = s % 3;
        if (s == nst - 1) cp_wait0(); else cp_wait1();
        __syncthreads();
        if (s + 2 < nst) issue_stage(s + 2, (s + 2) % 3);

        uint32_t bA = sbase + (uint32_t)buf * STG_B;
        uint32_t bB = bA + 18432;

        #pragma unroll
        for (int kk = 0; kk < 4; kk++) {
            uint32_t a[4][4];
            #pragma unroll
            for (int mt = 0; mt < 4; mt++)
                ldsm4(a[mt][0], a[mt][1], a[mt][2], a[mt][3],
                      bA + a_off + (uint32_t)(mt * 16 * PITCH_B) + (kk << 5));
            uint32_t b[4][4];
            #pragma unroll
            for (int bt = 0; bt < 4; bt++)
                ldsm4(b[bt][0], b[bt][1], b[bt][2], b[bt][3],
                      bB + b_off + (uint32_t)(bt * 16 * PITCH_B) + (kk << 5));
            #pragma unroll
            for (int mt = 0; mt < 4; mt++)
                #pragma unroll
                for (int bt = 0; bt < 4; bt++) {
                    mma16(acc[mt][bt * 2 + 0], a[mt][0], a[mt][1], a[mt][2], a[mt][3],
                          b[bt][0], b[bt][1]);
                    mma16(acc[mt][bt * 2 + 1], a[mt][0], a[mt][1], a[mt][2], a[mt][3],
                          b[bt][2], b[bt][3]);
                }
        }
    }

    // ---- epilogue ----
    #pragma unroll
    for (int mt = 0; mt < 4; mt++) {
        #pragma unroll
        for (int h = 0; h < 2; h++) {
            int row  = m0 + (warp_m << 6) + (mt << 4) + lr + (h << 3);
            int orow = (MODE == 3) ? winrow_to_orig(row) : row;
            #pragma unroll
            for (int nt = 0; nt < 8; nt++) {
                int c = (warp_n << 6) + (nt << 3) + (lc << 1);
                float2 bv = *(const float2*)(bias + n0 + c);
                float v0 = acc[mt][nt][h * 2 + 0] + bv.x;
                float v1 = acc[mt][nt][h * 2 + 1] + bv.y;
                if (MODE == 1) {
                    v0 = 0.5f * v0 * (1.0f + erff(v0 * 0.70710678118654752f));
                    v1 = 0.5f * v1 * (1.0f + erff(v1 * 0.70710678118654752f));
                }
                if (MODE <= 1) {
                    __half2* dst = (__half2*)((__half*)Cv + (size_t)orow * N + n0 + c);
                    *dst = __floats2half2_rn(v0, v1);
                } else {
                    size_t cb = (size_t)orow * N + n0 + c;
                    float2 rv = *(const float2*)(res + cb);
                    float2 o; o.x = v0 + rv.x; o.y = v1 + rv.y;
                    *(float2*)((float*)Cv + cb) = o;
                }
            }
        }
    }
}

// ---------------- attention: fp16 smem, pitch 40 halves (80 B, 16-aligned) --
__global__ void __launch_bounds__(128, 6) attn_kernel(
    const __half* __restrict__ qkv, const float* __restrict__ bfused,
    __half* __restrict__ o)
{
    int bh   = blockIdx.x;
    int wi   = bh / NHEAD;
    int head = bh - wi * NHEAD;
    int w    = wi & 63;
    int tid  = threadIdx.x;
    int lane = tid & 31;
    int wid  = tid >> 5;           // 0..3
    int type = (((w >> 3) == 7) ? 2 : 0) + (((w & 7) == 7) ? 1 : 0);

    __shared__ __align__(16) __half qs[49 * 40];
    __shared__ __align__(16) __half ks[49 * 40];
    __shared__ __align__(16) __half vs[49 * 40];
    __shared__ float  S [49][49];

    // pure uint4 copy: 49 rows x 4 chunks of 16B per matrix
    size_t base = (size_t)wi * 49 * 1152 + head * 32;
    for (int e = tid; e < 196; e += 128) {
        int n = e >> 2, c = e & 3;
        const __half* src = qkv + base + (size_t)n * 1152 + (c << 3);
        *(uint4*)&qs[n * 40 + (c << 3)] = *(const uint4*)(src);
        *(uint4*)&ks[n * 40 + (c << 3)] = *(const uint4*)(src + 384);
        *(uint4*)&vs[n * 40 + (c << 3)] = *(const uint4*)(src + 768);
    }
    __syncthreads();

    const float* Bf = bfused + (size_t)(type * NHEAD + head) * 2401;

    // QK^T (SCALE folded into result) + fused bias + softmax: warp per row
    for (int i = wid; i < 49; i += 4) {
        float2 q[16];
        {
            const uint4* qr = (const uint4*)&qs[i * 40];
            #pragma unroll
            for (int c = 0; c < 4; c++) {
                uint4 u = qr[c];
                const __half2* h = (const __half2*)&u;
                q[c * 4 + 0] = __half22float2(h[0]);
                q[c * 4 + 1] = __half22float2(h[1]);
                q[c * 4 + 2] = __half22float2(h[2]);
                q[c * 4 + 3] = __half22float2(h[3]);
            }
        }
        const float* Br = Bf + i * 49;

        float sv0, sv1;
        {
            int j = lane;
            const uint4* kr = (const uint4*)&ks[j * 40];
            float s = 0.0f;
            #pragma unroll
            for (int c = 0; c < 4; c++) {
                uint4 u = kr[c];
                const __half2* h = (const __half2*)&u;
                #pragma unroll
                for (int t = 0; t < 4; t++) {
                    float2 f = __half22float2(h[t]);
                    s += q[c * 4 + t].x * f.x + q[c * 4 + t].y * f.y;
                }
            }
            sv0 = s * SCALE + Br[j];
        }
        if (lane < 17) {
            int j = lane + 32;
            const uint4* kr = (const uint4*)&ks[j * 40];
            float s = 0.0f;
            #pragma unroll
            for (int c = 0; c < 4; c++) {
                uint4 u = kr[c];
                const __half2* h = (const __half2*)&u;
                #pragma unroll
                for (int t = 0; t < 4; t++) {
                    float2 f = __half22float2(h[t]);
                    s += q[c * 4 + t].x * f.x + q[c * 4 + t].y * f.y;
                }
            }
            sv1 = s * SCALE + Br[j];
        } else sv1 = -1e30f;

        float mx = fmaxf(sv0, sv1);
        #pragma unroll
        for (int off = 16; off; off >>= 1) mx = fmaxf(mx, __shfl_xor_sync(~0u, mx, off));
        float e0 = __expf(sv0 - mx);
        float e1 = (lane < 17) ? __expf(sv1 - mx) : 0.0f;
        float sm = e0 + e1;
        #pragma unroll
        for (int off = 16; off; off >>= 1) sm += __shfl_xor_sync(~0u, sm, off);
        float inv = 1.0f / sm;
        S[i][lane] = e0 * inv;
        if (lane < 17) S[i][lane + 32] = e1 * inv;
    }
    __syncthreads();

    // AV: task = d8*49 + i (consecutive lanes -> consecutive rows, same d8)
    size_t obase = (size_t)wi * 49 * 384 + head * 32;
    for (int task = tid; task < 196; task += 128) {
        int d8 = task / 49, i = task - d8 * 49;
        float a0=0,a1=0,a2=0,a3=0,a4=0,a5=0,a6=0,a7=0;
        #pragma unroll 7
        for (int j = 0; j < 49; j++) {
            float s = S[i][j];
            uint4 u = *(const uint4*)&vs[j * 40 + (d8 << 3)];
            const __half2* h = (const __half2*)&u;
            float2 f0 = __half22float2(h[0]);
            float2 f1 = __half22float2(h[1]);
            float2 f2 = __half22float2(h[2]);
            float2 f3 = __half22float2(h[3]);
            a0 += s * f0.x; a1 += s * f0.y;
            a2 += s * f1.x; a3 += s * f1.y;
            a4 += s * f2.x; a5 += s * f2.y;
            a6 += s * f3.x; a7 += s * f3.y;
        }
        uint4 out;
        __half2* oh = (__half2*)&out;
        oh[0] = __floats2half2_rn(a0, a1);
        oh[1] = __floats2half2_rn(a2, a3);
        oh[2] = __floats2half2_rn(a4, a5);
        oh[3] = __floats2half2_rn(a6, a7);
        *(uint4*)&o[obase + (size_t)i * 384 + (d8 << 3)] = out;
    }
}

// ---------------- host launch ----------------------------------------------
extern "C" void kernel_launch(void* const* d_in, const int* in_sizes, int n_in,
                              void* d_out, int out_size)
{
    const float* x       = (const float*)d_in[0];
    const float* ln1_g   = (const float*)d_in[1];
    const float* ln1_b   = (const float*)d_in[2];
    const float* qkv_w   = (const float*)d_in[3];
    const float* qkv_b   = (const float*)d_in[4];
    const float* proj_w  = (const float*)d_in[5];
    const float* proj_b  = (const float*)d_in[6];
    const float* bias_tb = (const float*)d_in[7];
    const float* ln2_g   = (const float*)d_in[8];
    const float* ln2_b   = (const float*)d_in[9];
    const float* fc1_w   = (const float*)d_in[10];
    const float* fc1_b   = (const float*)d_in[11];
    const float* fc2_w   = (const float*)d_in[12];
    const float* fc2_b   = (const float*)d_in[13];
    float*       out     = (float*)d_out;

    __half *ph, *pqkv, *po, *py, *pu, *pwt;
    float  *pxa, *pbias;
    cudaGetSymbolAddress((void**)&ph,   g_h);
    cudaGetSymbolAddress((void**)&pqkv, g_qkv);
    cudaGetSymbolAddress((void**)&po,   g_o);
    cudaGetSymbolAddress((void**)&pxa,  g_xa);
    cudaGetSymbolAddress((void**)&py,   g_y);
    cudaGetSymbolAddress((void**)&pu,   g_u);
    cudaGetSymbolAddress((void**)&pwt,  g_wt);
    cudaGetSymbolAddress((void**)&pbias, g_bias);

    cudaFuncSetAttribute(tc_gemm<0>, cudaFuncAttributeMaxDynamicSharedMemorySize, SMEM_SZ);
    cudaFuncSetAttribute(tc_gemm<1>, cudaFuncAttributeMaxDynamicSharedMemorySize, SMEM_SZ);
    cudaFuncSetAttribute(tc_gemm<2>, cudaFuncAttributeMaxDynamicSharedMemorySize, SMEM_SZ);
    cudaFuncSetAttribute(tc_gemm<3>, cudaFuncAttributeMaxDynamicSharedMemorySize, SMEM_SZ);

    // 1. LN1 + shift + window gather -> fp16
    ln_kernel<1><<<TOK / 4, 128>>>(x, ln1_g, ln1_b, ph);

    // 0a. all weight transposes in one launch
    transpose_all<<<1728, 256>>>(qkv_w, proj_w, fc1_w, fc2_w, pwt);

    // 0b. fused bias+mask tables (4 types x 12 heads)
    prep_bias<<<4 * NHEAD, 256>>>(bias_tb, pbias);

    // 2. qkv GEMM [100352 x 1152], K=384 -> fp16
    tc_gemm<0><<<dim3(9, TOK / 128), 128, SMEM_SZ>>>(ph, pwt + WT_QKV, qkv_b, nullptr, pqkv, 1152, 384);

    // 3. windowed attention -> fp16
    attn_kernel<<<2048 * NHEAD, 128>>>(pqkv, pbias, po);

    // 4. proj GEMM + window-reverse scatter + residual(x) -> fp32 xa
    tc_gemm<3><<<dim3(3, TOK / 128), 128, SMEM_SZ>>>(po, pwt + WT_PROJ, proj_b, x, pxa, 384, 384);

    // 5. LN2 -> fp16
    ln_kernel<0><<<TOK / 4, 128>>>(pxa, ln2_g, ln2_b, py);

    // 6. fc1 GEMM + gelu, N=1536 -> fp16
    tc_gemm<1><<<dim3(12, TOK / 128), 128, SMEM_SZ>>>(py, pwt + WT_FC1, fc1_b, nullptr, pu, 1536, 384);

    // 7. fc2 GEMM + residual -> fp32 out, K=1536
    tc_gemm<2><<<dim3(3, TOK / 128), 128, SMEM_SZ>>>(pu, pwt + WT_FC2, fc2_b, pxa, out, 384, 1536);
}